// round 14
// baseline (speedup 1.0000x reference)
#include <cuda_runtime.h>
#include <cuda_bf16.h>
#include <cstdint>

#define T_STEPS 512
#define HID 64
#define NBW 8         // batches per WARP (warp fully owns its recurrence)
#define KPAD 72       // bf16 per h-row (144B) — R10-proven padding
#define SXP 17        // sx row pad (floats) — odd stride for staging conflicts

__device__ __forceinline__ float tanh_fast(float x) {
    float e; asm("ex2.approx.f32 %0, %1;" : "=f"(e) : "f"(x * 2.885390082f)); // 2*log2(e)
    float r; asm("rcp.approx.f32 %0, %1;" : "=f"(r) : "f"(e + 1.0f));
    return fmaf(-2.0f, r, 1.0f);
}

// accurate split for loop-invariant W: w = hi + lo (packed bf16x2)
__device__ __forceinline__ void split2(float a, float b, uint32_t &uhi, uint32_t &ulo) {
    __nv_bfloat16 ah = __float2bfloat16_rn(a), bh = __float2bfloat16_rn(b);
    float ar = a - __bfloat162float(ah), br = b - __bfloat162float(bh);
    __nv_bfloat16 al = __float2bfloat16_rn(ar), bl = __float2bfloat16_rn(br);
    uhi = ((uint32_t)__bfloat16_as_ushort(bh) << 16) | __bfloat16_as_ushort(ah);
    ulo = ((uint32_t)__bfloat16_as_ushort(bl) << 16) | __bfloat16_as_ushort(al);
}

__device__ __forceinline__ void mma16816(float d[4], const uint32_t a[4], uint32_t b0, uint32_t b1) {
    asm volatile("mma.sync.aligned.m16n8k16.row.col.f32.bf16.bf16.f32 "
        "{%0,%1,%2,%3}, {%4,%5,%6,%7}, {%8,%9}, {%0,%1,%2,%3};"
        : "+f"(d[0]), "+f"(d[1]), "+f"(d[2]), "+f"(d[3])
        : "r"(a[0]), "r"(a[1]), "r"(a[2]), "r"(a[3]), "r"(b0), "r"(b1));
}

// WARP-AUTONOMOUS RNN: each warp owns ALL 64 rows x 8 batches of its recurrence.
// No __syncthreads in the recurrence at all — only __syncwarp. 2 independent
// warps per CTA (SMSP 0/1), grid=128 -> 1 CTA/SM, every warp free-runs.
__global__ void __launch_bounds__(64)
rnn_warpauto_kernel(const float* __restrict__ x,
                    const float* __restrict__ W_ih,
                    const float* __restrict__ W_hh,
                    const float* __restrict__ b_ih,
                    const float* __restrict__ b_hh,
                    const float* __restrict__ fc_w,
                    const float* __restrict__ fc_b,
                    float* __restrict__ out)
{
    __shared__ __align__(16) float sx[T_STEPS][SXP];                  // cols 0-15 used
    __shared__ __align__(16) __nv_bfloat16 hbuf[2][2][2][NBW][KPAD];  // [warp][pp][split][n][k]

    const int lane = threadIdx.x & 31, w = threadIdx.x >> 5;
    const int g = lane >> 2, q = lane & 3;
    const int c0 = 2 * q, c1 = 2 * q + 1;          // local batch cols
    const int cw0 = 8 * w + c0, cw1 = 8 * w + c1;  // cols in sx
    const int b0 = blockIdx.x * (2 * NBW) + 8 * w; // this warp's first batch

    // ---- A fragments for ALL 4 M-tiles: rows 16mt+g, 16mt+g+8 (128 regs) ----
    uint32_t Ahi[4][4][4], Alo[4][4][4];
#pragma unroll
    for (int mt = 0; mt < 4; ++mt) {
        int r0 = 16 * mt + g, r1 = r0 + 8;
#pragma unroll
        for (int kt = 0; kt < 4; ++kt) {
            int kb = kt * 16 + 2 * q;
            split2(W_hh[r0 * HID + kb],     W_hh[r0 * HID + kb + 1], Ahi[mt][kt][0], Alo[mt][kt][0]);
            split2(W_hh[r1 * HID + kb],     W_hh[r1 * HID + kb + 1], Ahi[mt][kt][1], Alo[mt][kt][1]);
            split2(W_hh[r0 * HID + kb + 8], W_hh[r0 * HID + kb + 9], Ahi[mt][kt][2], Alo[mt][kt][2]);
            split2(W_hh[r1 * HID + kb + 8], W_hh[r1 * HID + kb + 9], Ahi[mt][kt][3], Alo[mt][kt][3]);
        }
    }
    float wih0[4], wih1[4], bi0[4], bi1[4];
#pragma unroll
    for (int mt = 0; mt < 4; ++mt) {
        int r0 = 16 * mt + g, r1 = r0 + 8;
        wih0[mt] = W_ih[r0];  wih1[mt] = W_ih[r1];
        bi0[mt] = b_ih[r0] + b_hh[r0];  bi1[mt] = b_ih[r1] + b_hh[r1];
    }

    // ---- stage this warp's x (8 batches x 512) into sx cols [8w, 8w+8) ----
#pragma unroll 1
    for (int nn = 0; nn < NBW; ++nn) {
        const float4* xr = reinterpret_cast<const float4*>(x + (size_t)(b0 + nn) * T_STEPS);
#pragma unroll
        for (int j = 0; j < 4; ++j) {
            float4 v = xr[lane + 32 * j];
            int t4 = 4 * (lane + 32 * j);
            sx[t4 + 0][8 * w + nn] = v.x;  sx[t4 + 1][8 * w + nn] = v.y;
            sx[t4 + 2][8 * w + nn] = v.z;  sx[t4 + 3][8 * w + nn] = v.w;
        }
    }
    __syncwarp();

    // trunc split + store h value at (row r, local col nn) into hbuf[w][pp]
    auto put_h = [&](int pp, int r, int nn, float hv) {
        uint32_t u = __float_as_uint(hv);
        float lo = hv - __uint_as_float(u & 0xFFFF0000u);
        uint32_t ul = __float_as_uint(lo);
        *reinterpret_cast<unsigned short*>(&hbuf[w][pp][0][nn][r]) = (unsigned short)(u >> 16);
        *reinterpret_cast<unsigned short*>(&hbuf[w][pp][1][nn][r]) = (unsigned short)(ul >> 16);
    };

    // ---- t=0: h(0) = tanh(x W_ih + bias) -> pp=1 ----
    {
        float xa = sx[0][cw0], xb = sx[0][cw1];
#pragma unroll
        for (int mt = 0; mt < 4; ++mt) {
            int r0 = 16 * mt + g, r1 = r0 + 8;
            put_h(1, r0, c0, tanh_fast(fmaf(wih0[mt], xa, bi0[mt])));
            put_h(1, r0, c1, tanh_fast(fmaf(wih0[mt], xb, bi0[mt])));
            put_h(1, r1, c0, tanh_fast(fmaf(wih1[mt], xa, bi1[mt])));
            put_h(1, r1, c1, tanh_fast(fmaf(wih1[mt], xb, bi1[mt])));
        }
    }
    __syncwarp();

    // ---- recurrence: fully intra-warp, one __syncwarp per step ----
#pragma unroll 1
    for (int t = 1; t < T_STEPS; ++t) {
        const int cur = t & 1, nxt = cur ^ 1;

        uint32_t Bhi[4][2], Blo[4][2];
#pragma unroll
        for (int kt = 0; kt < 4; ++kt) {
            int kb = kt * 16 + 2 * q;
            Bhi[kt][0] = *reinterpret_cast<const uint32_t*>(&hbuf[w][cur][0][g][kb]);
            Bhi[kt][1] = *reinterpret_cast<const uint32_t*>(&hbuf[w][cur][0][g][kb + 8]);
            Blo[kt][0] = *reinterpret_cast<const uint32_t*>(&hbuf[w][cur][1][g][kb]);
            Blo[kt][1] = *reinterpret_cast<const uint32_t*>(&hbuf[w][cur][1][g][kb + 8]);
        }

        float xa = sx[t][cw0], xb = sx[t][cw1];
        float dA[4][4], dE[4][4];   // dA: Whi*h_hi (+xp init); dE: Whi*h_lo + Wlo*h_hi
#pragma unroll
        for (int mt = 0; mt < 4; ++mt) {
            dA[mt][0] = fmaf(wih0[mt], xa, bi0[mt]);
            dA[mt][1] = fmaf(wih0[mt], xb, bi0[mt]);
            dA[mt][2] = fmaf(wih1[mt], xa, bi1[mt]);
            dA[mt][3] = fmaf(wih1[mt], xb, bi1[mt]);
            dE[mt][0] = dE[mt][1] = dE[mt][2] = dE[mt][3] = 0.0f;
        }
#pragma unroll
        for (int kt = 0; kt < 4; ++kt)
#pragma unroll
            for (int mt = 0; mt < 4; ++mt) {
                mma16816(dA[mt], Ahi[mt][kt], Bhi[kt][0], Bhi[kt][1]);
                mma16816(dE[mt], Ahi[mt][kt], Blo[kt][0], Blo[kt][1]);
                mma16816(dE[mt], Alo[mt][kt], Bhi[kt][0], Bhi[kt][1]);
            }

#pragma unroll
        for (int mt = 0; mt < 4; ++mt) {
            int r0 = 16 * mt + g, r1 = r0 + 8;
            put_h(nxt, r0, c0, tanh_fast(dA[mt][0] + dE[mt][0]));
            put_h(nxt, r0, c1, tanh_fast(dA[mt][1] + dE[mt][1]));
            put_h(nxt, r1, c0, tanh_fast(dA[mt][2] + dE[mt][2]));
            put_h(nxt, r1, c1, tanh_fast(dA[mt][3] + dE[mt][3]));
        }
        __syncwarp();
    }

    // ---- FC: h(T-1) in pp=0 (T even). Lanes 0-7 each own one batch column. ----
    if (lane < NBW) {
        float s = 0.0f;
#pragma unroll
        for (int r = 0; r < HID; ++r) {
            float hv = __bfloat162float(hbuf[w][0][0][lane][r]) +
                       __bfloat162float(hbuf[w][0][1][lane][r]);
            s = fmaf(fc_w[r], hv, s);
        }
        out[b0 + lane] = s + fc_b[0];
    }
}

extern "C" void kernel_launch(void* const* d_in, const int* in_sizes, int n_in,
                              void* d_out, int out_size)
{
    const float* x    = (const float*)d_in[0];  // [B, T, 1]
    const float* W_ih = (const float*)d_in[1];  // [64, 1]
    const float* W_hh = (const float*)d_in[2];  // [64, 64]
    const float* b_ih = (const float*)d_in[3];  // [64]
    const float* b_hh = (const float*)d_in[4];  // [64]
    const float* fc_w = (const float*)d_in[5];  // [1, 64]
    const float* fc_b = (const float*)d_in[6];  // [1]
    float* out = (float*)d_out;                 // [B, 1]

    int B = in_sizes[0] / T_STEPS;              // I == 1
    rnn_warpauto_kernel<<<B / (2 * NBW), 64>>>(x, W_ih, W_hh, b_ih, b_hh, fc_w, fc_b, out);
}

// round 15
// speedup vs baseline: 1.5649x; 1.5649x over previous
#include <cuda_runtime.h>
#include <cuda_bf16.h>
#include <cstdint>

#define T_STEPS 512
#define HID 64
#define NB 16         // batches per CTA (one 16-batch chain per SM)
#define KPAD 72       // bf16 elems per h-row: 144B = 36 words -> conflict-free B frags

__device__ __forceinline__ float tanh_fast(float x) {
    float e; asm("ex2.approx.f32 %0, %1;" : "=f"(e) : "f"(x * 2.885390082f)); // 2*log2(e)
    float r; asm("rcp.approx.f32 %0, %1;" : "=f"(r) : "f"(e + 1.0f));
    return fmaf(-2.0f, r, 1.0f);
}

// accurate split for loop-invariant W: w = hi + lo (packed bf16x2)
__device__ __forceinline__ void split2(float a, float b, uint32_t &uhi, uint32_t &ulo) {
    __nv_bfloat16 ah = __float2bfloat16_rn(a), bh = __float2bfloat16_rn(b);
    float ar = a - __bfloat162float(ah), br = b - __bfloat162float(bh);
    __nv_bfloat16 al = __float2bfloat16_rn(ar), bl = __float2bfloat16_rn(bh == bh ? br : br); // br
    uhi = ((uint32_t)__bfloat16_as_ushort(bh) << 16) | __bfloat16_as_ushort(ah);
    ulo = ((uint32_t)__bfloat16_as_ushort(bl) << 16) | __bfloat16_as_ushort(al);
}

// Ampere-style bf16 MMA, fp32 accumulate: arch-neutral PTX (works on plain sm_103).
__device__ __forceinline__ void mma16816(float d[4], const uint32_t a[4], uint32_t b0, uint32_t b1) {
    asm volatile("mma.sync.aligned.m16n8k16.row.col.f32.bf16.bf16.f32 "
        "{%0,%1,%2,%3}, {%4,%5,%6,%7}, {%8,%9}, {%0,%1,%2,%3};"
        : "+f"(d[0]), "+f"(d[1]), "+f"(d[2]), "+f"(d[3])
        : "r"(a[0]), "r"(a[1]), "r"(a[2]), "r"(a[3]), "r"(b0), "r"(b1));
}

// MERGED-CHAIN kernel: R13 measured that 2 co-resident CTAs SERIALIZE their
// barrier-to-barrier chains (2 x 8-batch steps per ~513cyc). So: ONE CTA of
// 8 warps / 16 batches / ONE barrier per step -> one chain serves 16 batches.
// warp wid: M-tile mt = wid&3 (rows 16mt..16mt+15), n-half nh = wid>>2 (batch
// cols 8nh..8nh+7). Per-warp work identical to R13 (12 MMA, 4 tanh).
__global__ void __launch_bounds__(256, 1)
rnn_hmma_merged_kernel(const float* __restrict__ x,
                       const float* __restrict__ W_ih,
                       const float* __restrict__ W_hh,
                       const float* __restrict__ b_ih,
                       const float* __restrict__ b_hh,
                       const float* __restrict__ fc_w,
                       const float* __restrict__ fc_b,
                       float* __restrict__ out)
{
    __shared__ __align__(16) float sx[T_STEPS][NB];                 // x transposed, 32KB
    __shared__ __align__(16) __nv_bfloat16 hbuf[2][2][NB][KPAD];    // [pingpong][split][n][k]
    __shared__ float red[4][NB];

    const int tid  = threadIdx.x;
    const int lane = tid & 31, wid = tid >> 5;      // 8 warps
    const int g = lane >> 2, q = lane & 3;
    const int mt = wid & 3, nh = wid >> 2;
    const int r0 = mt * 16 + g, r1 = r0 + 8;        // this thread's two M rows
    const int c0 = nh * 8 + 2 * q, c1 = c0 + 1;     // this thread's two batch cols (global)
    const int bg = nh * 8 + g;                      // B-frag batch col (global)
    const int b0 = blockIdx.x * NB;

    // ---- loop-invariant A fragments: W_hh rows r0/r1, hi+lo bf16 splits (32 regs) ----
    uint32_t Ahi[4][4], Alo[4][4];
#pragma unroll
    for (int kt = 0; kt < 4; ++kt) {
        int kb = kt * 16 + 2 * q;
        split2(W_hh[r0 * HID + kb],     W_hh[r0 * HID + kb + 1],     Ahi[kt][0], Alo[kt][0]);
        split2(W_hh[r1 * HID + kb],     W_hh[r1 * HID + kb + 1],     Ahi[kt][1], Alo[kt][1]);
        split2(W_hh[r0 * HID + kb + 8], W_hh[r0 * HID + kb + 9],     Ahi[kt][2], Alo[kt][2]);
        split2(W_hh[r1 * HID + kb + 8], W_hh[r1 * HID + kb + 9],     Ahi[kt][3], Alo[kt][3]);
    }

    const float wih0 = W_ih[r0],             wih1 = W_ih[r1];
    const float bi0  = b_ih[r0] + b_hh[r0],  bi1  = b_ih[r1] + b_hh[r1];
    const float fw0  = fc_w[r0],             fw1  = fc_w[r1];

    // ---- stage x transposed: sx[t][n]  (I=1 -> each batch is 512 contiguous floats) ----
    {
        const float4* xg = reinterpret_cast<const float4*>(x + (size_t)b0 * T_STEPS);
        for (int i = tid; i < NB * (T_STEPS / 4); i += 256) {
            int bb = i >> 7, t4 = (i & 127) * 4;
            float4 v = xg[(i >> 7) * 128 + (i & 127)];
            sx[t4 + 0][bb] = v.x; sx[t4 + 1][bb] = v.y;
            sx[t4 + 2][bb] = v.z; sx[t4 + 3][bb] = v.w;
        }
    }
    __syncthreads();

    // fast trunc split + store: hi = top16(h), lo = h - hi (exact), lo16 = top16(lo)
    auto store_h = [&](int pp, const float hv[4]) {
        const int nn[4] = {c0, c1, c0, c1};
        const int mm[4] = {r0, r0, r1, r1};
#pragma unroll
        for (int i = 0; i < 4; ++i) {
            uint32_t u = __float_as_uint(hv[i]);
            float lo = hv[i] - __uint_as_float(u & 0xFFFF0000u);
            uint32_t ul = __float_as_uint(lo);
            *reinterpret_cast<unsigned short*>(&hbuf[pp][0][nn[i]][mm[i]]) = (unsigned short)(u >> 16);
            *reinterpret_cast<unsigned short*>(&hbuf[pp][1][nn[i]][mm[i]]) = (unsigned short)(ul >> 16);
        }
    };

    // ---- t=0: h(0) = tanh(x*W_ih + bias) -> hbuf[1] ----
    float h0, h1, h2, h3;
    {
        float xa = sx[0][c0], xb = sx[0][c1];
        h0 = tanh_fast(fmaf(wih0, xa, bi0));  h1 = tanh_fast(fmaf(wih0, xb, bi0));
        h2 = tanh_fast(fmaf(wih1, xa, bi1));  h3 = tanh_fast(fmaf(wih1, xb, bi1));
        float hv[4] = {h0, h1, h2, h3};
        store_h(1, hv);
    }
    __syncthreads();

    // ---- recurrence: ONE __syncthreads per step, one 16-batch chain ----
#pragma unroll 1
    for (int t = 1; t < T_STEPS; ++t) {
        const int cur = t & 1, nxt = cur ^ 1;

        // init dA chain with xp (off the critical chain)
        float2 xv = *reinterpret_cast<const float2*>(&sx[t][c0]);
        float dA[4] = { fmaf(wih0, xv.x, bi0), fmaf(wih0, xv.y, bi0),
                        fmaf(wih1, xv.x, bi1), fmaf(wih1, xv.y, bi1) };
        float dB[4] = {0, 0, 0, 0}, dC[4] = {0, 0, 0, 0};

        uint32_t Bhi[4][2], Blo[4][2];
#pragma unroll
        for (int kt = 0; kt < 4; ++kt) {
            int kb = kt * 16 + 2 * q;
            Bhi[kt][0] = *reinterpret_cast<const uint32_t*>(&hbuf[cur][0][bg][kb]);
            Bhi[kt][1] = *reinterpret_cast<const uint32_t*>(&hbuf[cur][0][bg][kb + 8]);
            Blo[kt][0] = *reinterpret_cast<const uint32_t*>(&hbuf[cur][1][bg][kb]);
            Blo[kt][1] = *reinterpret_cast<const uint32_t*>(&hbuf[cur][1][bg][kb + 8]);
        }
#pragma unroll
        for (int kt = 0; kt < 4; ++kt) {
            mma16816(dA, Ahi[kt], Bhi[kt][0], Bhi[kt][1]);   // Whi * h_hi  (+xp init)
            mma16816(dB, Ahi[kt], Blo[kt][0], Blo[kt][1]);   // Whi * h_lo
            mma16816(dC, Alo[kt], Bhi[kt][0], Bhi[kt][1]);   // Wlo * h_hi
        }

        h0 = tanh_fast(dA[0] + (dB[0] + dC[0]));  // (r0, c0)
        h1 = tanh_fast(dA[1] + (dB[1] + dC[1]));  // (r0, c1)
        h2 = tanh_fast(dA[2] + (dB[2] + dC[2]));  // (r1, c0)
        h3 = tanh_fast(dA[3] + (dB[3] + dC[3]));  // (r1, c1)

        float hv[4] = {h0, h1, h2, h3};
        store_h(nxt, hv);
        __syncthreads();
    }

    // ---- FC on h(T-1) held in regs: out[n] = sum_m fc_w[m] h[m][n] + fc_b ----
    float p0 = fmaf(fw0, h0, fw1 * h2);   // n = c0
    float p1 = fmaf(fw0, h1, fw1 * h3);   // n = c1
#pragma unroll
    for (int o = 4; o < 32; o <<= 1) {    // reduce over g-groups (lanes with same q)
        p0 += __shfl_xor_sync(0xffffffffu, p0, o);
        p1 += __shfl_xor_sync(0xffffffffu, p1, o);
    }
    if (lane < 4) { red[mt][c0] = p0; red[mt][c1] = p1; }   // per-(mt, n-half) partials
    __syncthreads();
    if (tid < NB)
        out[b0 + tid] = red[0][tid] + red[1][tid] + red[2][tid] + red[3][tid] + fc_b[0];
}

extern "C" void kernel_launch(void* const* d_in, const int* in_sizes, int n_in,
                              void* d_out, int out_size)
{
    const float* x    = (const float*)d_in[0];  // [B, T, 1]
    const float* W_ih = (const float*)d_in[1];  // [64, 1]
    const float* W_hh = (const float*)d_in[2];  // [64, 64]
    const float* b_ih = (const float*)d_in[3];  // [64]
    const float* b_hh = (const float*)d_in[4];  // [64]
    const float* fc_w = (const float*)d_in[5];  // [1, 64]
    const float* fc_b = (const float*)d_in[6];  // [1]
    float* out = (float*)d_out;                 // [B, 1]

    int B = in_sizes[0] / T_STEPS;              // I == 1
    rnn_hmma_merged_kernel<<<B / NB, 256>>>(x, W_ih, W_hh, b_ih, b_hh, fc_w, fc_b, out);
}

// round 16
// speedup vs baseline: 1.6375x; 1.0464x over previous
#include <cuda_runtime.h>
#include <cuda_bf16.h>
#include <cstdint>

#define T_STEPS 512
#define HID 64
#define NB 8          // batches per CTA
#define KW 68         // words per h-row: STS banks 8q+g injective (conflict-free),
                      // LDS.64 pairs spread evenly (exactly 2 wavefronts)

__device__ __forceinline__ float tanh_fast(float x) {
    float e; asm("ex2.approx.f32 %0, %1;" : "=f"(e) : "f"(x * 2.885390082f)); // 2*log2(e)
    float r; asm("rcp.approx.f32 %0, %1;" : "=f"(r) : "f"(e + 1.0f));
    return fmaf(-2.0f, r, 1.0f);
}

// accurate split for loop-invariant W: w = hi + lo (packed bf16x2)
__device__ __forceinline__ void split2(float a, float b, uint32_t &uhi, uint32_t &ulo) {
    __nv_bfloat16 ah = __float2bfloat16_rn(a), bh = __float2bfloat16_rn(b);
    float ar = a - __bfloat162float(ah), br = b - __bfloat162float(bh);
    __nv_bfloat16 al = __float2bfloat16_rn(ar), bl = __float2bfloat16_rn(br);
    uhi = ((uint32_t)__bfloat16_as_ushort(bh) << 16) | __bfloat16_as_ushort(ah);
    ulo = ((uint32_t)__bfloat16_as_ushort(bl) << 16) | __bfloat16_as_ushort(al);
}

// Ampere-style bf16 MMA, fp32 accumulate (arch-neutral PTX, works on plain sm_103).
__device__ __forceinline__ void mma16816(float d[4], const uint32_t a[4], uint32_t b0, uint32_t b1) {
    asm volatile("mma.sync.aligned.m16n8k16.row.col.f32.bf16.bf16.f32 "
        "{%0,%1,%2,%3}, {%4,%5,%6,%7}, {%8,%9}, {%0,%1,%2,%3};"
        : "+f"(d[0]), "+f"(d[1]), "+f"(d[2]), "+f"(d[3])
        : "r"(a[0]), "r"(a[1]), "r"(a[2]), "r"(a[3]), "r"(b0), "r"(b1));
}

// split barrier (named bar 1): 128 arrives + 128 syncs = 256 per phase
#define BARX_ARRIVE() asm volatile("bar.arrive 1, 256;" ::: "memory")
#define BARX_SYNC()   asm volatile("bar.sync 1, 256;"   ::: "memory")

// R13 base + chain cuts: packed h words (4 STS.32 / 8 LDS.64 instead of
// 8 STS.16 / 16 LDS.32) and split-barrier with next-step prep in the shadow.
__global__ void __launch_bounds__(128, 2)
rnn_hmma_kernel(const float* __restrict__ x,
                const float* __restrict__ W_ih,
                const float* __restrict__ W_hh,
                const float* __restrict__ b_ih,
                const float* __restrict__ b_hh,
                const float* __restrict__ fc_w,
                const float* __restrict__ fc_b,
                float* __restrict__ out)
{
    __shared__ __align__(16) float sx[T_STEPS][NB];       // x transposed, 16KB
    __shared__ __align__(16) uint32_t hw[2][NB][KW];      // [pingpong][n][k] word = hi|lo<<16
    __shared__ float red[4][NB];

    const int tid  = threadIdx.x;
    const int lane = tid & 31, wid = tid >> 5;
    const int g = lane >> 2, q = lane & 3;       // fragment coords
    const int mb = wid * 16;
    const int r0 = mb + g, r1 = mb + g + 8;      // this thread's two M rows
    const int c0 = 2 * q, c1 = 2 * q + 1;        // this thread's two N cols (batches)
    const int b0 = blockIdx.x * NB;

    // ---- loop-invariant A fragments: W_hh rows r0/r1, hi+lo bf16 splits (32 regs) ----
    uint32_t Ahi[4][4], Alo[4][4];
#pragma unroll
    for (int kt = 0; kt < 4; ++kt) {
        int kb = kt * 16 + 2 * q;
        split2(W_hh[r0 * HID + kb],     W_hh[r0 * HID + kb + 1],     Ahi[kt][0], Alo[kt][0]);
        split2(W_hh[r1 * HID + kb],     W_hh[r1 * HID + kb + 1],     Ahi[kt][1], Alo[kt][1]);
        split2(W_hh[r0 * HID + kb + 8], W_hh[r0 * HID + kb + 9],     Ahi[kt][2], Alo[kt][2]);
        split2(W_hh[r1 * HID + kb + 8], W_hh[r1 * HID + kb + 9],     Ahi[kt][3], Alo[kt][3]);
    }

    const float wih0 = W_ih[r0],             wih1 = W_ih[r1];
    const float bi0  = b_ih[r0] + b_hh[r0],  bi1  = b_ih[r1] + b_hh[r1];
    const float fw0  = fc_w[r0],             fw1  = fc_w[r1];

    // ---- stage x transposed: sx[t][n] ----
    {
        const float4* xg = reinterpret_cast<const float4*>(x + (size_t)b0 * T_STEPS);
        for (int i = tid; i < NB * (T_STEPS / 4); i += 128) {
            int bb = i >> 7, t4 = (i & 127) * 4;
            float4 v = xg[(i >> 7) * 128 + (i & 127)];
            sx[t4 + 0][bb] = v.x; sx[t4 + 1][bb] = v.y;
            sx[t4 + 2][bb] = v.z; sx[t4 + 3][bb] = v.w;
        }
    }
    __syncthreads();

    // trunc split + packed store: word = (u>>16) | (ul>>16)<<16 via one PRMT
    auto store_h = [&](int pp, const float hv[4]) {
        const int nn[4] = {c0, c1, c0, c1};
        const int mm[4] = {r0, r0, r1, r1};
#pragma unroll
        for (int i = 0; i < 4; ++i) {
            uint32_t u = __float_as_uint(hv[i]);
            float lo = hv[i] - __uint_as_float(u & 0xFFFF0000u);   // exact residual
            uint32_t ul = __float_as_uint(lo);
            hw[pp][nn[i]][mm[i]] = __byte_perm(u, ul, 0x7632);     // hi | lo<<16
        }
    };

    // ---- t=0: h(0) = tanh(x*W_ih + bias) -> hw[1] ----
    float h0, h1, h2, h3;
    {
        float xa = sx[0][c0], xb = sx[0][c1];
        h0 = tanh_fast(fmaf(wih0, xa, bi0));  h1 = tanh_fast(fmaf(wih0, xb, bi0));
        h2 = tanh_fast(fmaf(wih1, xa, bi1));  h3 = tanh_fast(fmaf(wih1, xb, bi1));
        float hv[4] = {h0, h1, h2, h3};
        store_h(1, hv);
    }
    BARX_ARRIVE();

    // prep for t=1 in the barrier shadow
    float2 xv = *reinterpret_cast<const float2*>(&sx[1][c0]);
    float dA[4] = { fmaf(wih0, xv.x, bi0), fmaf(wih0, xv.y, bi0),
                    fmaf(wih1, xv.x, bi1), fmaf(wih1, xv.y, bi1) };
    float dB[4] = {0, 0, 0, 0}, dC[4] = {0, 0, 0, 0};

    // ---- recurrence ----
#pragma unroll 1
    for (int t = 1; t < T_STEPS; ++t) {
        const int cur = t & 1, nxt = cur ^ 1;
        BARX_SYNC();                             // pairs with previous arrive

        // B frags: 8 LDS.64 from packed words + PRMT hi/lo splits
        uint32_t Bhi[4][2], Blo[4][2];
#pragma unroll
        for (int kt = 0; kt < 4; ++kt) {
            int kb = kt * 16 + 2 * q;
            uint2 wa = *reinterpret_cast<const uint2*>(&hw[cur][g][kb]);
            uint2 wb = *reinterpret_cast<const uint2*>(&hw[cur][g][kb + 8]);
            Bhi[kt][0] = __byte_perm(wa.x, wa.y, 0x5410);
            Blo[kt][0] = __byte_perm(wa.x, wa.y, 0x7632);
            Bhi[kt][1] = __byte_perm(wb.x, wb.y, 0x5410);
            Blo[kt][1] = __byte_perm(wb.x, wb.y, 0x7632);
        }
#pragma unroll
        for (int kt = 0; kt < 4; ++kt) {
            mma16816(dA, Ahi[kt], Bhi[kt][0], Bhi[kt][1]);   // Whi * h_hi  (+xp init)
            mma16816(dB, Ahi[kt], Blo[kt][0], Blo[kt][1]);   // Whi * h_lo
            mma16816(dC, Alo[kt], Bhi[kt][0], Bhi[kt][1]);   // Wlo * h_hi
        }

        h0 = tanh_fast(dA[0] + (dB[0] + dC[0]));  // (r0, c0)
        h1 = tanh_fast(dA[1] + (dB[1] + dC[1]));  // (r0, c1)
        h2 = tanh_fast(dA[2] + (dB[2] + dC[2]));  // (r1, c0)
        h3 = tanh_fast(dA[3] + (dB[3] + dC[3]));  // (r1, c1)

        float hv[4] = {h0, h1, h2, h3};
        store_h(nxt, hv);
        BARX_ARRIVE();

        // next-step prep in the barrier shadow (t=511 tail reads sx[0], unused)
        float2 xn = *reinterpret_cast<const float2*>(&sx[(t + 1) & (T_STEPS - 1)][c0]);
        dA[0] = fmaf(wih0, xn.x, bi0);  dA[1] = fmaf(wih0, xn.y, bi0);
        dA[2] = fmaf(wih1, xn.x, bi1);  dA[3] = fmaf(wih1, xn.y, bi1);
        dB[0] = dB[1] = dB[2] = dB[3] = 0.0f;
        dC[0] = dC[1] = dC[2] = dC[3] = 0.0f;
    }

    // ---- FC on h(T-1) held in regs: out[n] = sum_m fc_w[m] h[m][n] + fc_b ----
    float p0 = fmaf(fw0, h0, fw1 * h2);   // n = c0
    float p1 = fmaf(fw0, h1, fw1 * h3);   // n = c1
#pragma unroll
    for (int o = 4; o < 32; o <<= 1) {    // reduce over g-groups (lanes with same q)
        p0 += __shfl_xor_sync(0xffffffffu, p0, o);
        p1 += __shfl_xor_sync(0xffffffffu, p1, o);
    }
    if (lane < 4) { red[wid][c0] = p0; red[wid][c1] = p1; }
    __syncthreads();
    if (tid < NB)
        out[b0 + tid] = red[0][tid] + red[1][tid] + red[2][tid] + red[3][tid] + fc_b[0];
}

extern "C" void kernel_launch(void* const* d_in, const int* in_sizes, int n_in,
                              void* d_out, int out_size)
{
    const float* x    = (const float*)d_in[0];  // [B, T, 1]
    const float* W_ih = (const float*)d_in[1];  // [64, 1]
    const float* W_hh = (const float*)d_in[2];  // [64, 64]
    const float* b_ih = (const float*)d_in[3];  // [64]
    const float* b_hh = (const float*)d_in[4];  // [64]
    const float* fc_w = (const float*)d_in[5];  // [1, 64]
    const float* fc_b = (const float*)d_in[6];  // [1]
    float* out = (float*)d_out;                 // [B, 1]

    int B = in_sizes[0] / T_STEPS;              // I == 1
    rnn_hmma_kernel<<<B / NB, 128>>>(x, W_ih, W_hh, b_ih, b_hh, fc_w, fc_b, out);
}

// round 17
// speedup vs baseline: 1.7387x; 1.0618x over previous
#include <cuda_runtime.h>
#include <cuda_bf16.h>
#include <cstdint>

#define T_STEPS 512
#define HID 64
#define NB 8          // batches per CTA
#define KPAD 72       // bf16 elems per h-row: 144B = 36 words -> LDS.32 bank (4g+q) injective

__device__ __forceinline__ float tanh_fast(float x) {
    float e; asm("ex2.approx.f32 %0, %1;" : "=f"(e) : "f"(x * 2.885390082f)); // 2*log2(e)
    float r; asm("rcp.approx.f32 %0, %1;" : "=f"(r) : "f"(e + 1.0f));
    return fmaf(-2.0f, r, 1.0f);
}

// accurate split for loop-invariant W: w = hi + lo (packed bf16x2)
__device__ __forceinline__ void split2(float a, float b, uint32_t &uhi, uint32_t &ulo) {
    __nv_bfloat16 ah = __float2bfloat16_rn(a), bh = __float2bfloat16_rn(b);
    float ar = a - __bfloat162float(ah), br = b - __bfloat162float(bh);
    __nv_bfloat16 al = __float2bfloat16_rn(ar), bl = __float2bfloat16_rn(br);
    uhi = ((uint32_t)__bfloat16_as_ushort(bh) << 16) | __bfloat16_as_ushort(ah);
    ulo = ((uint32_t)__bfloat16_as_ushort(bl) << 16) | __bfloat16_as_ushort(al);
}

// Ampere-style bf16 MMA, fp32 accumulate (arch-neutral PTX, works on plain sm_103).
__device__ __forceinline__ void mma16816(float d[4], const uint32_t a[4], uint32_t b0, uint32_t b1) {
    asm volatile("mma.sync.aligned.m16n8k16.row.col.f32.bf16.bf16.f32 "
        "{%0,%1,%2,%3}, {%4,%5,%6,%7}, {%8,%9}, {%0,%1,%2,%3};"
        : "+f"(d[0]), "+f"(d[1]), "+f"(d[2]), "+f"(d[3])
        : "r"(a[0]), "r"(a[1]), "r"(a[2]), "r"(a[3]), "r"(b0), "r"(b1));
}

// split barrier (named bar 1): 128 arrives + 128 syncs = 256 per phase
#define BARX_ARRIVE() asm volatile("bar.arrive 1, 256;" ::: "memory")
#define BARX_SYNC()   asm volatile("bar.sync 1, 256;"   ::: "memory")

// R17 = R13 conflict-free hi/lo layout (16 LDS.32 + 8 STS.16, zero PRMT)
//     + R16 split-barrier with next-step prep in the arrive->sync shadow.
// (R16's packed words had 2-way LDS.64 bank conflicts: bank 4g+2q degenerate ->
//  L1 50.6%; the separate arrays' LDS.32 bank 4g+q is injective -> L1 ~35%.)
__global__ void __launch_bounds__(128, 2)
rnn_hmma_kernel(const float* __restrict__ x,
                const float* __restrict__ W_ih,
                const float* __restrict__ W_hh,
                const float* __restrict__ b_ih,
                const float* __restrict__ b_hh,
                const float* __restrict__ fc_w,
                const float* __restrict__ fc_b,
                float* __restrict__ out)
{
    __shared__ __align__(16) float sx[T_STEPS][NB];                 // x transposed, 16KB
    __shared__ __align__(16) __nv_bfloat16 hbuf[2][2][NB][KPAD];    // [pingpong][split][n][k]
    __shared__ float red[4][NB];

    const int tid  = threadIdx.x;
    const int lane = tid & 31, wid = tid >> 5;
    const int g = lane >> 2, q = lane & 3;       // fragment coords
    const int mb = wid * 16;
    const int r0 = mb + g, r1 = mb + g + 8;      // this thread's two M rows
    const int c0 = 2 * q, c1 = 2 * q + 1;        // this thread's two N cols (batches)
    const int b0 = blockIdx.x * NB;

    // ---- loop-invariant A fragments: W_hh rows r0/r1, hi+lo bf16 splits (32 regs) ----
    uint32_t Ahi[4][4], Alo[4][4];
#pragma unroll
    for (int kt = 0; kt < 4; ++kt) {
        int kb = kt * 16 + 2 * q;
        split2(W_hh[r0 * HID + kb],     W_hh[r0 * HID + kb + 1],     Ahi[kt][0], Alo[kt][0]);
        split2(W_hh[r1 * HID + kb],     W_hh[r1 * HID + kb + 1],     Ahi[kt][1], Alo[kt][1]);
        split2(W_hh[r0 * HID + kb + 8], W_hh[r0 * HID + kb + 9],     Ahi[kt][2], Alo[kt][2]);
        split2(W_hh[r1 * HID + kb + 8], W_hh[r1 * HID + kb + 9],     Ahi[kt][3], Alo[kt][3]);
    }

    const float wih0 = W_ih[r0],             wih1 = W_ih[r1];
    const float bi0  = b_ih[r0] + b_hh[r0],  bi1  = b_ih[r1] + b_hh[r1];
    const float fw0  = fc_w[r0],             fw1  = fc_w[r1];

    // ---- stage x transposed: sx[t][n] ----
    {
        const float4* xg = reinterpret_cast<const float4*>(x + (size_t)b0 * T_STEPS);
        for (int i = tid; i < NB * (T_STEPS / 4); i += 128) {
            int bb = i >> 7, t4 = (i & 127) * 4;
            float4 v = xg[(i >> 7) * 128 + (i & 127)];
            sx[t4 + 0][bb] = v.x; sx[t4 + 1][bb] = v.y;
            sx[t4 + 2][bb] = v.z; sx[t4 + 3][bb] = v.w;
        }
    }
    __syncthreads();

    // trunc split + store: hi = top16(h), lo = h - hi (exact), lo16 = top16(lo)
    auto store_h = [&](int pp, const float hv[4]) {
        const int nn[4] = {c0, c1, c0, c1};
        const int mm[4] = {r0, r0, r1, r1};
#pragma unroll
        for (int i = 0; i < 4; ++i) {
            uint32_t u = __float_as_uint(hv[i]);
            float lo = hv[i] - __uint_as_float(u & 0xFFFF0000u);   // exact residual
            uint32_t ul = __float_as_uint(lo);
            *reinterpret_cast<unsigned short*>(&hbuf[pp][0][nn[i]][mm[i]]) = (unsigned short)(u >> 16);
            *reinterpret_cast<unsigned short*>(&hbuf[pp][1][nn[i]][mm[i]]) = (unsigned short)(ul >> 16);
        }
    };

    // ---- t=0: h(0) = tanh(x*W_ih + bias) -> hbuf[1] ----
    float h0, h1, h2, h3;
    {
        float xa = sx[0][c0], xb = sx[0][c1];
        h0 = tanh_fast(fmaf(wih0, xa, bi0));  h1 = tanh_fast(fmaf(wih0, xb, bi0));
        h2 = tanh_fast(fmaf(wih1, xa, bi1));  h3 = tanh_fast(fmaf(wih1, xb, bi1));
        float hv[4] = {h0, h1, h2, h3};
        store_h(1, hv);
    }
    BARX_ARRIVE();

    // prep for t=1 in the barrier shadow
    float2 xv = *reinterpret_cast<const float2*>(&sx[1][c0]);
    float dA[4] = { fmaf(wih0, xv.x, bi0), fmaf(wih0, xv.y, bi0),
                    fmaf(wih1, xv.x, bi1), fmaf(wih1, xv.y, bi1) };
    float dB[4] = {0, 0, 0, 0}, dC[4] = {0, 0, 0, 0};

    // ---- recurrence ----
#pragma unroll 1
    for (int t = 1; t < T_STEPS; ++t) {
        const int cur = t & 1, nxt = cur ^ 1;
        BARX_SYNC();                             // pairs with previous arrive

        // B frags: 16 conflict-free LDS.32 (bank = 4g+q, injective), no PRMT
        uint32_t Bhi[4][2], Blo[4][2];
#pragma unroll
        for (int kt = 0; kt < 4; ++kt) {
            int kb = kt * 16 + 2 * q;
            Bhi[kt][0] = *reinterpret_cast<const uint32_t*>(&hbuf[cur][0][g][kb]);
            Bhi[kt][1] = *reinterpret_cast<const uint32_t*>(&hbuf[cur][0][g][kb + 8]);
            Blo[kt][0] = *reinterpret_cast<const uint32_t*>(&hbuf[cur][1][g][kb]);
            Blo[kt][1] = *reinterpret_cast<const uint32_t*>(&hbuf[cur][1][g][kb + 8]);
        }
#pragma unroll
        for (int kt = 0; kt < 4; ++kt) {
            mma16816(dA, Ahi[kt], Bhi[kt][0], Bhi[kt][1]);   // Whi * h_hi  (+xp init)
            mma16816(dB, Ahi[kt], Blo[kt][0], Blo[kt][1]);   // Whi * h_lo
            mma16816(dC, Alo[kt], Bhi[kt][0], Bhi[kt][1]);   // Wlo * h_hi
        }

        h0 = tanh_fast(dA[0] + (dB[0] + dC[0]));  // (r0, c0)
        h1 = tanh_fast(dA[1] + (dB[1] + dC[1]));  // (r0, c1)
        h2 = tanh_fast(dA[2] + (dB[2] + dC[2]));  // (r1, c0)
        h3 = tanh_fast(dA[3] + (dB[3] + dC[3]));  // (r1, c1)

        float hv[4] = {h0, h1, h2, h3};
        store_h(nxt, hv);
        BARX_ARRIVE();

        // next-step prep in the barrier shadow (t=511 tail reads sx[0], unused)
        float2 xn = *reinterpret_cast<const float2*>(&sx[(t + 1) & (T_STEPS - 1)][c0]);
        dA[0] = fmaf(wih0, xn.x, bi0);  dA[1] = fmaf(wih0, xn.y, bi0);
        dA[2] = fmaf(wih1, xn.x, bi1);  dA[3] = fmaf(wih1, xn.y, bi1);
        dB[0] = dB[1] = dB[2] = dB[3] = 0.0f;
        dC[0] = dC[1] = dC[2] = dC[3] = 0.0f;
    }

    // ---- FC on h(T-1) held in regs: out[n] = sum_m fc_w[m] h[m][n] + fc_b ----
    float p0 = fmaf(fw0, h0, fw1 * h2);   // n = c0
    float p1 = fmaf(fw0, h1, fw1 * h3);   // n = c1
#pragma unroll
    for (int o = 4; o < 32; o <<= 1) {    // reduce over g-groups (lanes with same q)
        p0 += __shfl_xor_sync(0xffffffffu, p0, o);
        p1 += __shfl_xor_sync(0xffffffffu, p1, o);
    }
    if (lane < 4) { red[wid][c0] = p0; red[wid][c1] = p1; }
    __syncthreads();
    if (tid < NB)
        out[b0 + tid] = red[0][tid] + red[1][tid] + red[2][tid] + red[3][tid] + fc_b[0];
}

extern "C" void kernel_launch(void* const* d_in, const int* in_sizes, int n_in,
                              void* d_out, int out_size)
{
    const float* x    = (const float*)d_in[0];  // [B, T, 1]
    const float* W_ih = (const float*)d_in[1];  // [64, 1]
    const float* W_hh = (const float*)d_in[2];  // [64, 64]
    const float* b_ih = (const float*)d_in[3];  // [64]
    const float* b_hh = (const float*)d_in[4];  // [64]
    const float* fc_w = (const float*)d_in[5];  // [1, 64]
    const float* fc_b = (const float*)d_in[6];  // [1]
    float* out = (float*)d_out;                 // [B, 1]

    int B = in_sizes[0] / T_STEPS;              // I == 1
    rnn_hmma_kernel<<<B / NB, 128>>>(x, W_ih, W_hh, b_ih, b_hh, fc_w, fc_b, out);
}